// round 4
// baseline (speedup 1.0000x reference)
#include <cuda_runtime.h>
#include <cstdint>
#include <cstddef>

#define TT 512
#define BATCH 512
#define HH 128
#define G3 384

// ---------------- scratch (static __device__, no allocation) ----------------
__device__ float g_y0[(size_t)TT * BATCH * 256];            // layer0 output [t][b][256] (fwd|bwd)
__device__ float g_xp1[2][(size_t)TT * BATCH * G3];         // layer1 input projections per dir
__device__ float g_hcat[(size_t)BATCH * 256];               // final hiddens [b][256] (fwd|bwd)

// ---------------- helpers ----------------
__device__ __forceinline__ unsigned long long pack2(float x) {
    unsigned long long r;
    asm("mov.b64 %0, {%1, %1};" : "=l"(r) : "f"(x));
    return r;
}
__device__ __forceinline__ unsigned long long f2fma(unsigned long long a, unsigned long long b,
                                                    unsigned long long c) {
    unsigned long long d;
    asm("fma.rn.f32x2 %0, %1, %2, %3;" : "=l"(d) : "l"(a), "l"(b), "l"(c));
    return d;
}
__device__ __forceinline__ float lo32(unsigned long long v) {
    return __uint_as_float((unsigned)(v & 0xffffffffull));
}
__device__ __forceinline__ float hi32(unsigned long long v) {
    return __uint_as_float((unsigned)(v >> 32));
}
__device__ __forceinline__ float sigf(float x) {
    float e = __expf(-x);
    return __fdividef(1.0f, 1.0f + e);
}
__device__ __forceinline__ float tanhfast(float x) {
    float e = __expf(-2.0f * x);
    return __fdividef(2.0f, 1.0f + e) - 1.0f;
}

// ---------------- recurrent scan kernel ----------------
// Grid: 128 blocks. blocks 0..63 = forward dir batch tiles, 64..127 = backward.
// Block: 256 threads. thread = (j in 0..127 gate column, half in 0..1 row group).
// Each CTA owns 8 batch rows for the entire T=512 scan.
// Dynamic smem: w_hh transposed [128][384] fp32 = 192 KB.
template <int LAYER>
__global__ void __launch_bounds__(256, 1)
gru_scan(const float* __restrict__ x,
         const float* __restrict__ w_ih_f, const float* __restrict__ b_ih_f,
         const float* __restrict__ w_ih_b, const float* __restrict__ b_ih_b,
         const float* __restrict__ w_hh_f, const float* __restrict__ b_hh_f,
         const float* __restrict__ w_hh_b, const float* __restrict__ b_hh_b)
{
    extern __shared__ float wt[];                        // [k=128][j=384] transposed w_hh
    __shared__ __align__(16) float h_s[2][HH * 8];       // [buf][col*8 + row], double buffered

    const int bid = blockIdx.x;
    const int dir = bid >> 6;
    const int b0 = (bid & 63) * 8;
    const int tid = threadIdx.x;
    const int j = tid & 127;
    const int half = tid >> 7;

    const float* w_hh = dir ? w_hh_b : w_hh_f;
    const float* b_hh = dir ? b_hh_b : b_hh_f;

    // stage w_hh transposed into smem (coalesced gmem read, one-time strided smem write)
    for (int s = tid; s < HH * G3; s += 256) {
        int jj = s >> 7;         // row of w_hh (gate column)
        int k = s & 127;         // col of w_hh (h index)
        wt[k * G3 + jj] = w_hh[s];
    }
    for (int s = tid; s < HH * 8; s += 256) h_s[0][s] = 0.0f;

    // per-thread constants
    unsigned long long bp[3];
    bp[0] = pack2(b_hh[j]);
    bp[1] = pack2(b_hh[128 + j]);
    bp[2] = pack2(b_hh[256 + j]);

    float wih[3][4];
    float bih[3];
    if (LAYER == 0) {
        const float* w_ih = dir ? w_ih_b : w_ih_f;
        const float* b_ihp = dir ? b_ih_b : b_ih_f;
#pragma unroll
        for (int g = 0; g < 3; g++) {
            bih[g] = b_ihp[g * 128 + j];
#pragma unroll
            for (int f = 0; f < 4; f++) wih[g][f] = w_ih[(g * 128 + j) * 4 + f];
        }
    }

    float hreg[4] = {0.f, 0.f, 0.f, 0.f};
    __syncthreads();

    int cur = 0;
    for (int s = 0; s < TT; s++) {
        const int t = dir ? (TT - 1 - s) : s;

        // ---- prefetch input projections for this step (hidden under the matmul) ----
        float xp[3][4];
        if (LAYER == 0) {
#pragma unroll
            for (int r = 0; r < 4; r++) {
                int b = b0 + half * 4 + r;
                float4 xv = *(const float4*)(x + ((size_t)b * TT + t) * 4);
#pragma unroll
                for (int g = 0; g < 3; g++)
                    xp[g][r] = bih[g] + xv.x * wih[g][0] + xv.y * wih[g][1] +
                               xv.z * wih[g][2] + xv.w * wih[g][3];
            }
        } else {
#pragma unroll
            for (int r = 0; r < 4; r++) {
                int b = b0 + half * 4 + r;
                const float* p = &g_xp1[dir][((size_t)t * BATCH + b) * G3];
                xp[0][r] = p[j];
                xp[1][r] = p[128 + j];
                xp[2][r] = p[256 + j];
            }
        }

        // ---- phase 1: g = h @ w_hh^T + b_hh for my 3 columns x 4 rows (f32x2) ----
        unsigned long long acc[3][2];
#pragma unroll
        for (int g = 0; g < 3; g++) { acc[g][0] = bp[g]; acc[g][1] = bp[g]; }

        const float* hp = &h_s[cur][half * 4];
#pragma unroll 4
        for (int k = 0; k < HH; k++) {
            ulonglong2 hv = *(const ulonglong2*)(hp + k * 8);   // 4 rows = 2 f32x2 pairs (broadcast)
            unsigned long long w0 = pack2(wt[k * G3 + j]);
            unsigned long long w1 = pack2(wt[k * G3 + 128 + j]);
            unsigned long long w2 = pack2(wt[k * G3 + 256 + j]);
            acc[0][0] = f2fma(hv.x, w0, acc[0][0]);
            acc[0][1] = f2fma(hv.y, w0, acc[0][1]);
            acc[1][0] = f2fma(hv.x, w1, acc[1][0]);
            acc[1][1] = f2fma(hv.y, w1, acc[1][1]);
            acc[2][0] = f2fma(hv.x, w2, acc[2][0]);
            acc[2][1] = f2fma(hv.y, w2, acc[2][1]);
        }

        // ---- phase 2: gates + h update for my column j, 4 rows ----
        float hn4[4];
#pragma unroll
        for (int r = 0; r < 4; r++) {
            float gr = (r & 1) ? hi32(acc[0][r >> 1]) : lo32(acc[0][r >> 1]);
            float gz = (r & 1) ? hi32(acc[1][r >> 1]) : lo32(acc[1][r >> 1]);
            float gn = (r & 1) ? hi32(acc[2][r >> 1]) : lo32(acc[2][r >> 1]);
            float rr = sigf(xp[0][r] + gr);
            float zz = sigf(xp[1][r] + gz);
            float nn = tanhfast(xp[2][r] + rr * gn);
            float h = (1.0f - zz) * nn + zz * hreg[r];
            hreg[r] = h;
            hn4[r] = h;
        }
        const int nxt = cur ^ 1;
        *(float4*)&h_s[nxt][j * 8 + half * 4] = make_float4(hn4[0], hn4[1], hn4[2], hn4[3]);

        if (LAYER == 0) {
#pragma unroll
            for (int r = 0; r < 4; r++) {
                int b = b0 + half * 4 + r;
                g_y0[((size_t)t * BATCH + b) * 256 + dir * 128 + j] = hn4[r];
            }
        }
        __syncthreads();     // writes to h_s[nxt] visible; h_s[cur] reads all done
        cur = nxt;
    }

    if (LAYER == 1) {
#pragma unroll
        for (int r = 0; r < 4; r++) {
            int b = b0 + half * 4 + r;
            g_hcat[(size_t)b * 256 + dir * 128 + j] = hreg[r];
        }
    }
}

// ---------------- layer-1 input-projection GEMM ----------------
// xp1[dir][t][b][j] = b_ih[j] + sum_k y0[t][b][k] * w_ih[j][k]
// M = T*B = 262144, N = 384, K = 256. Tiles 128x128, 256 threads, 8x8 microtile, f32x2.
__global__ void __launch_bounds__(256)
gemm_xp1(const float* __restrict__ wf, const float* __restrict__ bf,
         const float* __restrict__ wb, const float* __restrict__ bb)
{
    const int dir = blockIdx.z;
    const float* W = dir ? wb : wf;
    const float* bias = dir ? bb : bf;
    const int M0 = blockIdx.x * 128;
    const int N0 = blockIdx.y * 128;

    __shared__ __align__(16) float As[2][16][128];
    __shared__ __align__(16) float Ws[2][16][128];

    const int tid = threadIdx.x;
    const int tx = tid & 15;
    const int ty = tid >> 4;
    const int lrow = tid >> 2;   // 0..63
    const int lc4 = tid & 3;     // 0..3

    const float* Abase = g_y0 + (size_t)M0 * 256;
    const float* Wbase = W + (size_t)N0 * 256;

    unsigned long long acc[8][4];
#pragma unroll
    for (int i = 0; i < 8; i++)
#pragma unroll
        for (int q = 0; q < 4; q++) acc[i][q] = 0ull;

    // preload chunk 0 into registers
    float4 aReg[2], wReg[2];
#pragma unroll
    for (int i = 0; i < 2; i++) {
        aReg[i] = *(const float4*)(Abase + (size_t)(lrow + i * 64) * 256 + lc4 * 4);
        wReg[i] = *(const float4*)(Wbase + (size_t)(lrow + i * 64) * 256 + lc4 * 4);
    }

    int buf = 0;
    for (int kc = 0; kc < 16; kc++) {
        // store prefetched chunk into smem[buf] (transposed to [k][m])
#pragma unroll
        for (int i = 0; i < 2; i++) {
            int row = lrow + i * 64;
            As[buf][lc4 * 4 + 0][row] = aReg[i].x;
            As[buf][lc4 * 4 + 1][row] = aReg[i].y;
            As[buf][lc4 * 4 + 2][row] = aReg[i].z;
            As[buf][lc4 * 4 + 3][row] = aReg[i].w;
            Ws[buf][lc4 * 4 + 0][row] = wReg[i].x;
            Ws[buf][lc4 * 4 + 1][row] = wReg[i].y;
            Ws[buf][lc4 * 4 + 2][row] = wReg[i].z;
            Ws[buf][lc4 * 4 + 3][row] = wReg[i].w;
        }
        __syncthreads();

        if (kc < 15) {
            int koff = (kc + 1) * 16 + lc4 * 4;
#pragma unroll
            for (int i = 0; i < 2; i++) {
                aReg[i] = *(const float4*)(Abase + (size_t)(lrow + i * 64) * 256 + koff);
                wReg[i] = *(const float4*)(Wbase + (size_t)(lrow + i * 64) * 256 + koff);
            }
        }

#pragma unroll
        for (int k = 0; k < 16; k++) {
            float4 a0 = *(const float4*)&As[buf][k][ty * 8];
            float4 a1 = *(const float4*)&As[buf][k][ty * 8 + 4];
            ulonglong2 bv0 = *(const ulonglong2*)&Ws[buf][k][tx * 8];
            ulonglong2 bv1 = *(const ulonglong2*)&Ws[buf][k][tx * 8 + 4];
            float av[8] = {a0.x, a0.y, a0.z, a0.w, a1.x, a1.y, a1.z, a1.w};
#pragma unroll
            for (int i = 0; i < 8; i++) {
                unsigned long long ap = pack2(av[i]);
                acc[i][0] = f2fma(ap, bv0.x, acc[i][0]);
                acc[i][1] = f2fma(ap, bv0.y, acc[i][1]);
                acc[i][2] = f2fma(ap, bv1.x, acc[i][2]);
                acc[i][3] = f2fma(ap, bv1.y, acc[i][3]);
            }
        }
        buf ^= 1;
    }

    // epilogue: add bias, store
    float bcol[8];
#pragma unroll
    for (int c = 0; c < 8; c++) bcol[c] = bias[N0 + tx * 8 + c];

    float* out = &g_xp1[dir][0] + (size_t)M0 * G3 + N0 + tx * 8;
#pragma unroll
    for (int i = 0; i < 8; i++) {
        int m = ty * 8 + i;
        float v[8];
#pragma unroll
        for (int q = 0; q < 4; q++) {
            v[2 * q + 0] = lo32(acc[i][q]) + bcol[2 * q + 0];
            v[2 * q + 1] = hi32(acc[i][q]) + bcol[2 * q + 1];
        }
        *(float4*)(out + (size_t)m * G3) = make_float4(v[0], v[1], v[2], v[3]);
        *(float4*)(out + (size_t)m * G3 + 4) = make_float4(v[4], v[5], v[6], v[7]);
    }
}

// ---------------- FC head ----------------
__global__ void __launch_bounds__(128)
head_kernel(const float* __restrict__ fc1w, const float* __restrict__ fc1b,
            const float* __restrict__ fc2w, const float* __restrict__ fc2b,
            float* __restrict__ out)
{
    __shared__ float hrow[256];
    __shared__ float a_s[128];
    const int b = blockIdx.x;
    const int tid = threadIdx.x;

    hrow[tid] = g_hcat[(size_t)b * 256 + tid];
    hrow[128 + tid] = g_hcat[(size_t)b * 256 + 128 + tid];
    __syncthreads();

    float s = fc1b[tid];
    const float* wr = fc1w + (size_t)tid * 256;
#pragma unroll 8
    for (int k = 0; k < 256; k++) s += hrow[k] * wr[k];
    a_s[tid] = fmaxf(s, 0.0f);
    __syncthreads();

    if (tid < 2) {
        float o = fc2b[tid];
#pragma unroll 8
        for (int k = 0; k < 128; k++) o += a_s[k] * fc2w[tid * 128 + k];
        out[b * 2 + tid] = o;
    }
}

// ---------------- launch ----------------
extern "C" void kernel_launch(void* const* d_in, const int* in_sizes, int n_in,
                              void* d_out, int out_size)
{
    (void)in_sizes; (void)n_in; (void)out_size;
    const float* x        = (const float*)d_in[0];
    const float* w_ih_l0f = (const float*)d_in[1];
    const float* w_hh_l0f = (const float*)d_in[2];
    const float* b_ih_l0f = (const float*)d_in[3];
    const float* b_hh_l0f = (const float*)d_in[4];
    const float* w_ih_l0b = (const float*)d_in[5];
    const float* w_hh_l0b = (const float*)d_in[6];
    const float* b_ih_l0b = (const float*)d_in[7];
    const float* b_hh_l0b = (const float*)d_in[8];
    const float* w_ih_l1f = (const float*)d_in[9];
    const float* w_hh_l1f = (const float*)d_in[10];
    const float* b_ih_l1f = (const float*)d_in[11];
    const float* b_hh_l1f = (const float*)d_in[12];
    const float* w_ih_l1b = (const float*)d_in[13];
    const float* w_hh_l1b = (const float*)d_in[14];
    const float* b_ih_l1b = (const float*)d_in[15];
    const float* b_hh_l1b = (const float*)d_in[16];
    const float* fc1_w    = (const float*)d_in[17];
    const float* fc1_b    = (const float*)d_in[18];
    const float* fc2_w    = (const float*)d_in[19];
    const float* fc2_b    = (const float*)d_in[20];

    const int smem = HH * G3 * (int)sizeof(float);  // 192 KB
    cudaFuncSetAttribute(gru_scan<0>, cudaFuncAttributeMaxDynamicSharedMemorySize, smem);
    cudaFuncSetAttribute(gru_scan<1>, cudaFuncAttributeMaxDynamicSharedMemorySize, smem);

    // layer 0: fused input projection + scan, both dirs (128 CTAs)
    gru_scan<0><<<128, 256, smem>>>(x, w_ih_l0f, b_ih_l0f, w_ih_l0b, b_ih_l0b,
                                    w_hh_l0f, b_hh_l0f, w_hh_l0b, b_hh_l0b);

    // layer 1 input projections (big parallel GEMM, both dirs)
    dim3 g(2048, 3, 2);
    gemm_xp1<<<g, 256>>>(w_ih_l1f, b_ih_l1f, w_ih_l1b, b_ih_l1b);

    // layer 1 scan (reads precomputed xp), both dirs
    gru_scan<1><<<128, 256, smem>>>(x, nullptr, nullptr, nullptr, nullptr,
                                    w_hh_l1f, b_hh_l1f, w_hh_l1b, b_hh_l1b);

    // FC head
    head_kernel<<<512, 128>>>(fc1_w, fc1_b, fc2_w, fc2_b, (float*)d_out);
}

// round 8
// speedup vs baseline: 1.3730x; 1.3730x over previous
#include <cuda_runtime.h>
#include <cstdint>
#include <cstddef>

#define TT 512
#define BATCH 512
#define HH 128
#define G3 384

// ---------------- scratch (static __device__, no allocation) ----------------
__device__ float g_y0[(size_t)TT * BATCH * 256];            // layer0 output [t][b][256] (fwd|bwd), tf32-rounded
__device__ float g_xp1[2][(size_t)TT * BATCH * G3];         // layer1 input projections per dir
__device__ float g_hcat[(size_t)BATCH * 256];               // final hiddens [b][256] (fwd|bwd)
__device__ float g_wtf[2][G3 * 256];                        // tf32-rounded layer1 w_ih per dir

// ---------------- helpers ----------------
__device__ __forceinline__ unsigned long long pack2(float x) {
    unsigned long long r;
    asm("mov.b64 %0, {%1, %1};" : "=l"(r) : "f"(x));
    return r;
}
__device__ __forceinline__ unsigned long long f2fma(unsigned long long a, unsigned long long b,
                                                    unsigned long long c) {
    unsigned long long d;
    asm("fma.rn.f32x2 %0, %1, %2, %3;" : "=l"(d) : "l"(a), "l"(b), "l"(c));
    return d;
}
__device__ __forceinline__ float lo32(unsigned long long v) {
    return __uint_as_float((unsigned)(v & 0xffffffffull));
}
__device__ __forceinline__ float hi32(unsigned long long v) {
    return __uint_as_float((unsigned)(v >> 32));
}
__device__ __forceinline__ float sigf(float x) {
    float e = __expf(-x);
    return __fdividef(1.0f, 1.0f + e);
}
__device__ __forceinline__ float tanhfast(float x) {
    float e = __expf(-2.0f * x);
    return __fdividef(2.0f, 1.0f + e) - 1.0f;
}
__device__ __forceinline__ float tf32_rna(float x) {
    uint32_t r;
    asm("cvt.rna.tf32.f32 %0, %1;" : "=r"(r) : "f"(x));
    return __uint_as_float(r);
}

// ---------------- recurrent scan kernel ----------------
// Grid: 128 blocks. blocks 0..63 = forward dir batch tiles, 64..127 = backward.
// Block: 256 threads. thread = (j in 0..127 gate column, half in 0..1 row group).
// Each CTA owns 8 batch rows for the entire T=512 scan.
// Dynamic smem: w_hh transposed [128][384] fp32 = 192 KB.
template <int LAYER>
__global__ void __launch_bounds__(256, 1)
gru_scan(const float* __restrict__ x,
         const float* __restrict__ w_ih_f, const float* __restrict__ b_ih_f,
         const float* __restrict__ w_ih_b, const float* __restrict__ b_ih_b,
         const float* __restrict__ w_hh_f, const float* __restrict__ b_hh_f,
         const float* __restrict__ w_hh_b, const float* __restrict__ b_hh_b)
{
    extern __shared__ float wt[];                        // [k=128][j=384] transposed w_hh
    __shared__ __align__(16) float h_s[2][HH * 8];       // [buf][col*8 + row], double buffered

    const int bid = blockIdx.x;
    const int dir = bid >> 6;
    const int b0 = (bid & 63) * 8;
    const int tid = threadIdx.x;
    const int j = tid & 127;
    const int half = tid >> 7;

    const float* w_hh = dir ? w_hh_b : w_hh_f;
    const float* b_hh = dir ? b_hh_b : b_hh_f;

    for (int s = tid; s < HH * G3; s += 256) {
        int jj = s >> 7;
        int k = s & 127;
        wt[k * G3 + jj] = w_hh[s];
    }
    for (int s = tid; s < HH * 8; s += 256) h_s[0][s] = 0.0f;

    unsigned long long bp[3];
    bp[0] = pack2(b_hh[j]);
    bp[1] = pack2(b_hh[128 + j]);
    bp[2] = pack2(b_hh[256 + j]);

    float wih[3][4];
    float bih[3];
    if (LAYER == 0) {
        const float* w_ih = dir ? w_ih_b : w_ih_f;
        const float* b_ihp = dir ? b_ih_b : b_ih_f;
#pragma unroll
        for (int g = 0; g < 3; g++) {
            bih[g] = b_ihp[g * 128 + j];
#pragma unroll
            for (int f = 0; f < 4; f++) wih[g][f] = w_ih[(g * 128 + j) * 4 + f];
        }
    }

    float hreg[4] = {0.f, 0.f, 0.f, 0.f};
    __syncthreads();

    int cur = 0;
    for (int s = 0; s < TT; s++) {
        const int t = dir ? (TT - 1 - s) : s;

        float xp[3][4];
        if (LAYER == 0) {
#pragma unroll
            for (int r = 0; r < 4; r++) {
                int b = b0 + half * 4 + r;
                float4 xv = *(const float4*)(x + ((size_t)b * TT + t) * 4);
#pragma unroll
                for (int g = 0; g < 3; g++)
                    xp[g][r] = bih[g] + xv.x * wih[g][0] + xv.y * wih[g][1] +
                               xv.z * wih[g][2] + xv.w * wih[g][3];
            }
        } else {
#pragma unroll
            for (int r = 0; r < 4; r++) {
                int b = b0 + half * 4 + r;
                const float* p = &g_xp1[dir][((size_t)t * BATCH + b) * G3];
                xp[0][r] = p[j];
                xp[1][r] = p[128 + j];
                xp[2][r] = p[256 + j];
            }
        }

        unsigned long long acc[3][2];
#pragma unroll
        for (int g = 0; g < 3; g++) { acc[g][0] = bp[g]; acc[g][1] = bp[g]; }

        const float* hp = &h_s[cur][half * 4];
#pragma unroll 4
        for (int k = 0; k < HH; k++) {
            ulonglong2 hv = *(const ulonglong2*)(hp + k * 8);
            unsigned long long w0 = pack2(wt[k * G3 + j]);
            unsigned long long w1 = pack2(wt[k * G3 + 128 + j]);
            unsigned long long w2 = pack2(wt[k * G3 + 256 + j]);
            acc[0][0] = f2fma(hv.x, w0, acc[0][0]);
            acc[0][1] = f2fma(hv.y, w0, acc[0][1]);
            acc[1][0] = f2fma(hv.x, w1, acc[1][0]);
            acc[1][1] = f2fma(hv.y, w1, acc[1][1]);
            acc[2][0] = f2fma(hv.x, w2, acc[2][0]);
            acc[2][1] = f2fma(hv.y, w2, acc[2][1]);
        }

        float hn4[4];
#pragma unroll
        for (int r = 0; r < 4; r++) {
            float gr = (r & 1) ? hi32(acc[0][r >> 1]) : lo32(acc[0][r >> 1]);
            float gz = (r & 1) ? hi32(acc[1][r >> 1]) : lo32(acc[1][r >> 1]);
            float gn = (r & 1) ? hi32(acc[2][r >> 1]) : lo32(acc[2][r >> 1]);
            float rr = sigf(xp[0][r] + gr);
            float zz = sigf(xp[1][r] + gz);
            float nn = tanhfast(xp[2][r] + rr * gn);
            float h = (1.0f - zz) * nn + zz * hreg[r];
            hreg[r] = h;
            hn4[r] = h;
        }
        const int nxt = cur ^ 1;
        *(float4*)&h_s[nxt][j * 8 + half * 4] = make_float4(hn4[0], hn4[1], hn4[2], hn4[3]);

        if (LAYER == 0) {
            // store tf32-RNA rounded so the tensor-core GEMM sees exact tf32 inputs
#pragma unroll
            for (int r = 0; r < 4; r++) {
                int b = b0 + half * 4 + r;
                g_y0[((size_t)t * BATCH + b) * 256 + dir * 128 + j] = tf32_rna(hn4[r]);
            }
        }
        __syncthreads();
        cur = nxt;
    }

    if (LAYER == 1) {
#pragma unroll
        for (int r = 0; r < 4; r++) {
            int b = b0 + half * 4 + r;
            g_hcat[(size_t)b * 256 + dir * 128 + j] = hreg[r];
        }
    }
}

// ---------------- pre-round layer1 input weights to tf32 ----------------
__global__ void __launch_bounds__(256)
round_w_kernel(const float* __restrict__ wf, const float* __restrict__ wb)
{
    int i = blockIdx.x * 256 + threadIdx.x;
    if (i < G3 * 256) {
        g_wtf[0][i] = tf32_rna(wf[i]);
        g_wtf[1][i] = tf32_rna(wb[i]);
    }
}

// ---------------- layer-1 input-projection GEMM (tf32 tensor cores) ----------------
// out[dir][m][n] = bias[n] + sum_k y0[m][k]*W[dir][n][k], M=262144, N=384(3 tiles), K=256
// CTA tile 128x128, BK=32 double-buffered via cp.async, 8 warps (2x4), warp tile m64n32.
#define BKP 36
#define ABYTES (128 * BKP * 4)      /* 18432 per operand per buffer */
#define BUFBYTES (2 * ABYTES)       /* 36864 per buffer (A+B) */

#define CP_ASYNC_CG(dst, src) \
    asm volatile("cp.async.cg.shared.global [%0], [%1], 16;" :: "r"(dst), "l"(src))

__global__ void __launch_bounds__(256, 2)
gemm_xp1_tc(const float* __restrict__ bf, const float* __restrict__ bb)
{
    extern __shared__ float sm[];
    const int nd = blockIdx.x;              // 0..5
    const int dir = nd & 1;
    const int N0 = (nd >> 1) * 128;
    const size_t M0 = (size_t)blockIdx.y * 128;

    const float* Ag = g_y0 + M0 * 256;
    const float* Wg = &g_wtf[dir][(size_t)N0 * 256];
    const float* bias = dir ? bb : bf;

    const int tid = threadIdx.x;
    const int lane = tid & 31;
    const int wid = tid >> 5;
    const int wm = wid >> 2;                // 0..1
    const int wn = wid & 3;                 // 0..3
    const int gID = lane >> 2;              // groupID
    const int tig = lane & 3;               // threadID_in_group

    const uint32_t smem_u = (uint32_t)__cvta_generic_to_shared(sm);

    float acc[4][4][4];
#pragma unroll
    for (int i = 0; i < 4; i++)
#pragma unroll
        for (int j2 = 0; j2 < 4; j2++)
#pragma unroll
            for (int r = 0; r < 4; r++) acc[i][j2][r] = 0.f;

    // ---- prologue: stage chunk 0 into buffer 0 ----
#pragma unroll
    for (int v = 0; v < 4; v++) {
        int idx = v * 256 + tid;
        int m = idx >> 3, kq = idx & 7;
        uint32_t so = smem_u + (uint32_t)(m * BKP + kq * 4) * 4;
        CP_ASYNC_CG(so, Ag + (size_t)m * 256 + kq * 4);
        CP_ASYNC_CG(so + ABYTES, Wg + (size_t)m * 256 + kq * 4);
    }
    asm volatile("cp.async.commit_group;");

    for (int kc = 0; kc < 8; kc++) {
        asm volatile("cp.async.wait_group 0;");
        __syncthreads();

        if (kc < 7) {
            const int buf = (kc + 1) & 1;
            const int ko = (kc + 1) * 32;
#pragma unroll
            for (int v = 0; v < 4; v++) {
                int idx = v * 256 + tid;
                int m = idx >> 3, kq = idx & 7;
                uint32_t so = smem_u + (uint32_t)(buf * BUFBYTES) + (uint32_t)(m * BKP + kq * 4) * 4;
                CP_ASYNC_CG(so, Ag + (size_t)m * 256 + ko + kq * 4);
                CP_ASYNC_CG(so + ABYTES, Wg + (size_t)m * 256 + ko + kq * 4);
            }
            asm volatile("cp.async.commit_group;");
        }

        const float* sA = sm + (kc & 1) * (BUFBYTES / 4);
        const float* sB = sA + (ABYTES / 4);

#pragma unroll
        for (int tk = 0; tk < 4; tk++) {
            uint32_t Afr[4][4];
            uint32_t Bfr[4][2];
#pragma unroll
            for (int tm = 0; tm < 4; tm++) {
                const float* p = sA + (wm * 64 + tm * 16 + gID) * BKP + tig + tk * 8;
                Afr[tm][0] = __float_as_uint(p[0]);
                Afr[tm][1] = __float_as_uint(p[8 * BKP]);
                Afr[tm][2] = __float_as_uint(p[4]);
                Afr[tm][3] = __float_as_uint(p[8 * BKP + 4]);
            }
#pragma unroll
            for (int tn = 0; tn < 4; tn++) {
                const float* p = sB + (wn * 32 + tn * 8 + gID) * BKP + tig + tk * 8;
                Bfr[tn][0] = __float_as_uint(p[0]);
                Bfr[tn][1] = __float_as_uint(p[4]);
            }
#pragma unroll
            for (int tm = 0; tm < 4; tm++)
#pragma unroll
                for (int tn = 0; tn < 4; tn++)
                    asm volatile(
                        "mma.sync.aligned.m16n8k8.row.col.f32.tf32.tf32.f32 "
                        "{%0,%1,%2,%3}, {%4,%5,%6,%7}, {%8,%9}, {%0,%1,%2,%3};"
                        : "+f"(acc[tm][tn][0]), "+f"(acc[tm][tn][1]),
                          "+f"(acc[tm][tn][2]), "+f"(acc[tm][tn][3])
                        : "r"(Afr[tm][0]), "r"(Afr[tm][1]), "r"(Afr[tm][2]), "r"(Afr[tm][3]),
                          "r"(Bfr[tn][0]), "r"(Bfr[tn][1]));
        }
        __syncthreads();
    }

    // ---- epilogue: bias + store ----
    float2 bv[4];
#pragma unroll
    for (int tn = 0; tn < 4; tn++) {
        int n = N0 + wn * 32 + tn * 8 + tig * 2;
        bv[tn].x = bias[n];
        bv[tn].y = bias[n + 1];
    }
    float* outp = &g_xp1[dir][0] + (M0 + wm * 64 + gID) * G3 + N0 + wn * 32 + tig * 2;
#pragma unroll
    for (int tm = 0; tm < 4; tm++) {
#pragma unroll
        for (int tn = 0; tn < 4; tn++) {
            float* o0 = outp + (size_t)(tm * 16) * G3 + tn * 8;
            float2 v0 = make_float2(acc[tm][tn][0] + bv[tn].x, acc[tm][tn][1] + bv[tn].y);
            float2 v1 = make_float2(acc[tm][tn][2] + bv[tn].x, acc[tm][tn][3] + bv[tn].y);
            *(float2*)o0 = v0;
            *(float2*)(o0 + 8 * G3) = v1;
        }
    }
}

// ---------------- FC head (coalesced, warp-reduce) ----------------
__global__ void __launch_bounds__(128)
head_kernel(const float* __restrict__ fc1w, const float* __restrict__ fc1b,
            const float* __restrict__ fc2w, const float* __restrict__ fc2b,
            float* __restrict__ out)
{
    __shared__ float hrow[256];
    __shared__ float a_s[128];
    const int b = blockIdx.x;
    const int tid = threadIdx.x;
    const int lane = tid & 31;
    const int wid = tid >> 5;

    hrow[tid] = g_hcat[(size_t)b * 256 + tid];
    hrow[128 + tid] = g_hcat[(size_t)b * 256 + 128 + tid];
    __syncthreads();

    for (int jj = 0; jj < 32; jj++) {
        int j = wid * 32 + jj;
        const float* wr = fc1w + (size_t)j * 256;
        float s = 0.f;
#pragma unroll
        for (int m = 0; m < 8; m++) s += hrow[lane + 32 * m] * wr[lane + 32 * m];
#pragma unroll
        for (int o = 16; o > 0; o >>= 1) s += __shfl_xor_sync(0xffffffffu, s, o);
        if (lane == 0) a_s[j] = fmaxf(s + fc1b[j], 0.f);
    }
    __syncthreads();

    if (wid < 2) {
        const float* wr = fc2w + wid * 128;
        float s = 0.f;
#pragma unroll
        for (int m = 0; m < 4; m++) s += a_s[lane + 32 * m] * wr[lane + 32 * m];
#pragma unroll
        for (int o = 16; o > 0; o >>= 1) s += __shfl_xor_sync(0xffffffffu, s, o);
        if (lane == 0) out[b * 2 + wid] = s + fc2b[wid];
    }
}

// ---------------- launch ----------------
extern "C" void kernel_launch(void* const* d_in, const int* in_sizes, int n_in,
                              void* d_out, int out_size)
{
    (void)in_sizes; (void)n_in; (void)out_size;
    const float* x        = (const float*)d_in[0];
    const float* w_ih_l0f = (const float*)d_in[1];
    const float* w_hh_l0f = (const float*)d_in[2];
    const float* b_ih_l0f = (const float*)d_in[3];
    const float* b_hh_l0f = (const float*)d_in[4];
    const float* w_ih_l0b = (const float*)d_in[5];
    const float* w_hh_l0b = (const float*)d_in[6];
    const float* b_ih_l0b = (const float*)d_in[7];
    const float* b_hh_l0b = (const float*)d_in[8];
    const float* w_ih_l1f = (const float*)d_in[9];
    const float* w_hh_l1f = (const float*)d_in[10];
    const float* b_ih_l1f = (const float*)d_in[11];
    const float* b_hh_l1f = (const float*)d_in[12];
    const float* w_ih_l1b = (const float*)d_in[13];
    const float* w_hh_l1b = (const float*)d_in[14];
    const float* b_ih_l1b = (const float*)d_in[15];
    const float* b_hh_l1b = (const float*)d_in[16];
    const float* fc1_w    = (const float*)d_in[17];
    const float* fc1_b    = (const float*)d_in[18];
    const float* fc2_w    = (const float*)d_in[19];
    const float* fc2_b    = (const float*)d_in[20];

    const int smem_scan = HH * G3 * (int)sizeof(float);  // 192 KB
    cudaFuncSetAttribute(gru_scan<0>, cudaFuncAttributeMaxDynamicSharedMemorySize, smem_scan);
    cudaFuncSetAttribute(gru_scan<1>, cudaFuncAttributeMaxDynamicSharedMemorySize, smem_scan);
    cudaFuncSetAttribute(gemm_xp1_tc, cudaFuncAttributeMaxDynamicSharedMemorySize, 2 * BUFBYTES);

    // pre-round layer1 input weights to tf32 (independent of scan0)
    round_w_kernel<<<(G3 * 256 + 255) / 256, 256>>>(w_ih_l1f, w_ih_l1b);

    // layer 0: fused input projection + scan, both dirs
    gru_scan<0><<<128, 256, smem_scan>>>(x, w_ih_l0f, b_ih_l0f, w_ih_l0b, b_ih_l0b,
                                         w_hh_l0f, b_hh_l0f, w_hh_l0b, b_hh_l0b);

    // layer 1 input projections on tensor cores (tf32)
    dim3 g(6, 2048, 1);
    gemm_xp1_tc<<<g, 256, 2 * BUFBYTES>>>(b_ih_l1f, b_ih_l1b);

    // layer 1 scan
    gru_scan<1><<<128, 256, smem_scan>>>(x, nullptr, nullptr, nullptr, nullptr,
                                         w_hh_l1f, b_hh_l1f, w_hh_l1b, b_hh_l1b);

    // FC head
    head_kernel<<<512, 128>>>(fc1_w, fc1_b, fc2_w, fc2_b, (float*)d_out);
}